// round 10
// baseline (speedup 1.0000x reference)
#include <cuda_runtime.h>
#include <cuda_bf16.h>
#include <cstdint>

#define LN_EPS 1e-5f
#define SEQ_L  256
#define KDIM   1024
#define NOUT   128

// ---------------- global scratch (no allocs allowed) ----------------
__device__ __align__(16) __nv_bfloat16 g_Ah[128 * 8192];  // x_down   hi [n][ij]
__device__ __align__(16) __nv_bfloat16 g_Al[128 * 8192];
__device__ __align__(16) __nv_bfloat16 g_Bh[128 * 8192];  // x_down_w hi [n][lm]
__device__ __align__(16) __nv_bfloat16 g_Bl[128 * 8192];
__device__ __align__(16) __nv_bfloat16 g_gWh[NOUT * KDIM];   // gamma*W hi [o][k]
__device__ __align__(16) unsigned char g_gWq[NOUT * KDIM];   // e4m3(gW * 2^-2)
__device__ __align__(16) unsigned char g_gWql[NOUT * KDIM];  // e4m3(gWlo * 2^7)
__device__ float g_cb[NOUT];
// normalized pair: hi bf16 [pair][k]; fp8 e4m3: np*2^-7 and npl*2^2
__device__ __align__(16) __nv_bfloat16 g_NpH[65536 * KDIM];
__device__ __align__(16) unsigned char g_Npq[65536 * KDIM];
__device__ __align__(16) unsigned char g_Npql[65536 * KDIM];

// ---------------- kernel A smem: 2 stages x (4 bufs x [32 n x 272 B]) ------
#define A_STAGE   34816
#define A_AH 0
#define A_AL 8704
#define A_BH 17408
#define A_BL 26112
#define OFF_NPH 0
#define OFF_NQ  33024
#define OFF_NQL 49408
#define SMEM_A_TOTAL 69632

// ---------------- kernel B smem: 3 stages x 32 KB -----
// per stage: NpH bf16 [128 x 64B] (swizzle c^((r>>1)&3)), fp8 tiles [128 x 32B]
#define S_NH  0
#define S_NQ  8192
#define S_NQL 12288
#define S_GH  16384
#define S_GQ  24576
#define S_GQL 28672
#define B_STAGE   32768
#define SMEM_B_TOTAL 98304

__device__ __forceinline__ uint32_t smem_u32(const void* p) {
    uint32_t a;
    asm("{ .reg .u64 t; cvta.to.shared.u64 t, %1; cvt.u32.u64 %0, t; }"
        : "=r"(a) : "l"(p));
    return a;
}
__device__ __forceinline__ void cp16(uint32_t dst, const void* src) {
    asm volatile("cp.async.cg.shared.global [%0], [%1], 16;"
                 :: "r"(dst), "l"(src) : "memory");
}
__device__ __forceinline__ void cp_commit() {
    asm volatile("cp.async.commit_group;" ::: "memory");
}
template <int N> __device__ __forceinline__ void cp_wait() {
    asm volatile("cp.async.wait_group %0;" :: "n"(N) : "memory");
}
__device__ __forceinline__ void ldmx4t(uint32_t* r, uint32_t addr) {
    asm volatile("ldmatrix.sync.aligned.m8n8.x4.trans.shared.b16 {%0,%1,%2,%3}, [%4];"
                 : "=r"(r[0]), "=r"(r[1]), "=r"(r[2]), "=r"(r[3]) : "r"(addr));
}
__device__ __forceinline__ void ldmx2t(uint32_t* r, uint32_t addr) {
    asm volatile("ldmatrix.sync.aligned.m8n8.x2.trans.shared.b16 {%0,%1}, [%2];"
                 : "=r"(r[0]), "=r"(r[1]) : "r"(addr));
}
__device__ __forceinline__ void ldmx4(uint32_t* r, uint32_t addr) {
    asm volatile("ldmatrix.sync.aligned.m8n8.x4.shared.b16 {%0,%1,%2,%3}, [%4];"
                 : "=r"(r[0]), "=r"(r[1]), "=r"(r[2]), "=r"(r[3]) : "r"(addr));
}
__device__ __forceinline__ void mma16816(float* c, const uint32_t* a, const uint32_t* b) {
    asm volatile(
        "mma.sync.aligned.m16n8k16.row.col.f32.bf16.bf16.f32 "
        "{%0,%1,%2,%3}, {%4,%5,%6,%7}, {%8,%9}, {%0,%1,%2,%3};"
        : "+f"(c[0]), "+f"(c[1]), "+f"(c[2]), "+f"(c[3])
        : "r"(a[0]), "r"(a[1]), "r"(a[2]), "r"(a[3]), "r"(b[0]), "r"(b[1]));
}
// fp8 e4m3 mma, K=32, fp32 accumulate (product scales arranged to 1)
__device__ __forceinline__ void qmma16832(float* c, const uint32_t* a, const uint32_t* b) {
    asm volatile(
        "mma.sync.aligned.m16n8k32.row.col.f32.e4m3.e4m3.f32 "
        "{%0,%1,%2,%3}, {%4,%5,%6,%7}, {%8,%9}, {%0,%1,%2,%3};"
        : "+f"(c[0]), "+f"(c[1]), "+f"(c[2]), "+f"(c[3])
        : "r"(a[0]), "r"(a[1]), "r"(a[2]), "r"(a[3]), "r"(b[0]), "r"(b[1]));
}
__device__ __forceinline__ uint32_t lds32(uint32_t a) {
    uint32_t v;
    asm volatile("ld.shared.b32 %0, [%1];" : "=r"(v) : "r"(a));
    return v;
}
__device__ __forceinline__ void sts16(uint32_t a, uint16_t v) {
    asm volatile("st.shared.u16 [%0], %1;" :: "r"(a), "h"(v) : "memory");
}
// pack: upper byte = hi, lower byte = lo
__device__ __forceinline__ uint16_t cvt_e4m3x2(float hi, float lo) {
    uint16_t r;
    asm("cvt.rn.satfinite.e4m3x2.f32 %0, %1, %2;" : "=h"(r) : "f"(hi), "f"(lo));
    return r;
}

// ---------------- prep: fp32 -> bf16 hi/lo (+ gW fp8) ----------------
__global__ void prep_all(const float* __restrict__ A, const float* __restrict__ B,
                         const float* __restrict__ gamma, const float* __restrict__ beta,
                         const float* __restrict__ W, const float* __restrict__ b) {
    if (blockIdx.x < 2048) {
        const unsigned v = blockIdx.x * 256 + threadIdx.x;  // float4 index
        const float4* src;
        __nv_bfloat16 *dh, *dl;
        unsigned i;
        if (v < 262144) { src = (const float4*)A; i = v; dh = g_Ah; dl = g_Al; }
        else            { src = (const float4*)B; i = v - 262144; dh = g_Bh; dl = g_Bl; }
        const float4 x = src[i];
        __nv_bfloat162 h01 = __floats2bfloat162_rn(x.x, x.y);
        __nv_bfloat162 h23 = __floats2bfloat162_rn(x.z, x.w);
        __nv_bfloat162 l01 = __floats2bfloat162_rn(x.x - __low2float(h01), x.y - __high2float(h01));
        __nv_bfloat162 l23 = __floats2bfloat162_rn(x.z - __low2float(h23), x.w - __high2float(h23));
        ((uint2*)dh)[i] = make_uint2(*(uint32_t*)&h01, *(uint32_t*)&h23);
        ((uint2*)dl)[i] = make_uint2(*(uint32_t*)&l01, *(uint32_t*)&l23);
    } else {
        const int o = blockIdx.x - 2048;
        const int t = threadIdx.x;
        float s = 0.f;
        for (int k = t; k < KDIM; k += 256) {
            const float wv = W[o * KDIM + k];
            const float gv = gamma[k] * wv;
            const __nv_bfloat16 h = __float2bfloat16(gv);
            g_gWh[o * KDIM + k] = h;
            const float gwl = gv - __bfloat162float(h);
            g_gWq[o * KDIM + k]  = (unsigned char)(cvt_e4m3x2(0.f, gv * 0.25f) & 0xFF);
            g_gWql[o * KDIM + k] = (unsigned char)(cvt_e4m3x2(0.f, gwl * 128.f) & 0xFF);
            s += beta[k] * wv;
        }
        __shared__ float red[256];
        red[t] = s;
        __syncthreads();
        for (int st = 128; st > 0; st >>= 1) {
            if (t < st) red[t] += red[t + st];
            __syncthreads();
        }
        if (t == 0) g_cb[o] = b[o] + red[0];
    }
}

// ---------------- kernel A: GEMM1 + LN -> g_NpH/g_Npq/g_Npql ----------
__global__ __launch_bounds__(256, 2)
void coevol_g1_kernel() {
    extern __shared__ char sm[];
    const uint32_t SB = smem_u32(sm);

    const int tid = threadIdx.x;
    const int lane = tid & 31, w = tid >> 5;
    const int bx = blockIdx.x, by = blockIdx.y;

    const int mbase = (w & 3) * 32;
    const int nbase = (w >> 2) * 64;
    float acc[2][8][4];
#pragma unroll
    for (int mt = 0; mt < 2; ++mt)
#pragma unroll
        for (int nt = 0; nt < 8; ++nt)
#pragma unroll
            for (int c = 0; c < 4; ++c) acc[mt][nt][c] = 0.f;

    const int g4 = lane >> 3;
    const int grow = lane & 7;
    const int kadd4 = (g4 >> 1) * 8, madd4 = (g4 & 1) * 8;
    const int kadd2 = (g4 & 1) * 8;

    auto stage_load = [&](int ch) {
        const uint32_t stg = SB + (uint32_t)(ch & 1) * A_STAGE;
#pragma unroll
        for (int it = 0; it < 8; ++it) {
            const int v = it * 256 + tid;
            const int buf = v >> 9;
            const int rem = v & 511;
            const int r = rem >> 4, c = rem & 15;
            const size_t srow = (size_t)(ch * 32 + r) * 16384;  // 8192 bf16/row
            const uint32_t dst = stg + (uint32_t)buf * 8704u
                               + (uint32_t)r * 272u + (uint32_t)c * 16u;
            const char* src;
            if (buf == 0)      src = (const char*)g_Ah + srow + bx * 256 + c * 16;
            else if (buf == 1) src = (const char*)g_Al + srow + bx * 256 + c * 16;
            else if (buf == 2) src = (const char*)g_Bh + srow + by * 256 + c * 16;
            else               src = (const char*)g_Bl + srow + by * 256 + c * 16;
            cp16(dst, src);
        }
    };

    stage_load(0);
    cp_commit();

    for (int ch = 0; ch < 4; ++ch) {
        cp_wait<0>();
        __syncthreads();
        if (ch < 3) { stage_load(ch + 1); cp_commit(); }

        const uint32_t stg = SB + (uint32_t)(ch & 1) * A_STAGE;
#pragma unroll
        for (int ks = 0; ks < 2; ++ks) {
            uint32_t ah[2][4], al[2][4];
#pragma unroll
            for (int mt = 0; mt < 2; ++mt) {
                const uint32_t aoff = (uint32_t)(ks * 16 + kadd4 + grow) * 272u
                                    + (uint32_t)(mbase + mt * 16 + madd4) * 2u;
                ldmx4t(ah[mt], stg + A_AH + aoff);
                ldmx4t(al[mt], stg + A_AL + aoff);
            }
#pragma unroll
            for (int nt = 0; nt < 8; ++nt) {
                uint32_t bh[2], bl[2];
                const uint32_t boff = (uint32_t)(ks * 16 + kadd2 + grow) * 272u
                                    + (uint32_t)(nbase + nt * 8) * 2u;
                ldmx2t(bh, stg + A_BH + boff);
                ldmx2t(bl, stg + A_BL + boff);
#pragma unroll
                for (int mt = 0; mt < 2; ++mt) {
                    mma16816(acc[mt][nt], ah[mt], bh);
                    mma16816(acc[mt][nt], ah[mt], bl);
                    mma16816(acc[mt][nt], al[mt], bh);
                }
            }
        }
    }
    __syncthreads();  // stage smem reuse for Np staging

    // ---------------- LayerNorm -> NpH bf16 + fp8 staging ----------
    const int i_loc = w & 3;
#pragma unroll
    for (int lb = 0; lb < 2; ++lb) {
        const int l_loc = (w >> 2) * 2 + lb;
        float sum = 0.f, sq = 0.f;
#pragma unroll
        for (int mt = 0; mt < 2; ++mt)
#pragma unroll
            for (int nt4 = 0; nt4 < 4; ++nt4)
#pragma unroll
                for (int c = 0; c < 4; ++c) {
                    const float v = acc[mt][lb * 4 + nt4][c];
                    sum += v;
                    sq = fmaf(v, v, sq);
                }
#pragma unroll
        for (int off = 16; off >= 1; off >>= 1) {
            sum += __shfl_xor_sync(0xffffffffu, sum, off);
            sq  += __shfl_xor_sync(0xffffffffu, sq, off);
        }
        const float mean = sum * (1.f / KDIM);
        const float var  = sq * (1.f / KDIM) - mean * mean;
        const float rstd = rsqrtf(var + LN_EPS);
        const int p = i_loc * 4 + l_loc;
#pragma unroll
        for (int mt = 0; mt < 2; ++mt)
#pragma unroll
            for (int nt4 = 0; nt4 < 4; ++nt4)
#pragma unroll
                for (int cp = 0; cp < 2; ++cp) {
                    const float f0 = (acc[mt][lb * 4 + nt4][cp * 2 + 0] - mean) * rstd;
                    const float f1 = (acc[mt][lb * 4 + nt4][cp * 2 + 1] - mean) * rstd;
                    __nv_bfloat162 h2 = __floats2bfloat162_rn(f0, f1);
                    const float l0 = f0 - __low2float(h2);
                    const float l1 = f1 - __high2float(h2);
                    const int j  = mt * 16 + (lane >> 2) + cp * 8;
                    const int mc = nt4 * 4 + (lane & 3);
                    const int idx = p * 516 + j * 16 + (mc ^ ((j & 3) << 2));
                    *(uint32_t*)(sm + OFF_NPH + idx * 4) = *(uint32_t*)&h2;
                    // fp8: low byte = element 2*mc, high = 2*mc+1
                    const uint32_t boff = (uint32_t)(p * 1024 + j * 32 + mc * 2);
                    sts16(SB + OFF_NQ + boff,
                          cvt_e4m3x2(f1 * 0.0078125f, f0 * 0.0078125f));
                    sts16(SB + OFF_NQL + boff,
                          cvt_e4m3x2(l1 * 4.f, l0 * 4.f));
                }
    }
    __syncthreads();

    // ---------------- copy staging -> global (coalesced) ----------
#pragma unroll
    for (int it = 0; it < 16; ++it) {
        const int v = it * 256 + tid;          // 0..4095 uint4
        if (v < 2048) {                        // NpH
            const int p = v >> 7;
            const int c4 = v & 127;
            const int wb = c4 * 4;
            const int j = wb >> 4, mc = wb & 15;
            const int sidx = p * 516 + j * 16 + (mc ^ ((j & 3) << 2));
            const uint32_t* s = (const uint32_t*)(sm + OFF_NPH) + sidx;
            uint4 val = make_uint4(s[0], s[1], s[2], s[3]);
            const int gi = bx * 4 + (p >> 2);
            const int gl = by * 4 + (p & 3);
            const size_t pair = (size_t)gi * SEQ_L + gl;
            ((uint4*)g_NpH)[pair * 128 + c4] = val;
        } else {                               // fp8 arrays
            const int arr = (v >= 3072);
            const int g = v - (arr ? 3072 : 2048);
            const int p = g >> 6;
            const int c4 = g & 63;
            uint4 val = *(const uint4*)(sm + (arr ? OFF_NQL : OFF_NQ) + p * 1024 + c4 * 16);
            const int gi = bx * 4 + (p >> 2);
            const int gl = by * 4 + (p & 3);
            const size_t pair = (size_t)gi * SEQ_L + gl;
            ((uint4*)(arr ? g_Npql : g_Npq))[pair * 64 + c4] = val;
        }
    }
}

// ---------------- kernel B: out = Np . gW + cb  (bf16 main + fp8 cross) ----
// Grid 512: CTA = 128 pairs x 128 o, K = 1024 in 32 chunks of 32.
__global__ __launch_bounds__(256, 2)
void coevol_g2_kernel(float* __restrict__ out) {
    extern __shared__ char sm[];
    const uint32_t SB = smem_u32(sm);

    const int tid = threadIdx.x;
    const int lane = tid & 31, w = tid >> 5;
    const int pb = blockIdx.x;

    const int mp = (w & 3) * 32;
    const int ob = (w >> 2) * 64;

    float acc[2][8][4];
#pragma unroll
    for (int mt = 0; mt < 2; ++mt)
#pragma unroll
        for (int nt = 0; nt < 8; ++nt)
#pragma unroll
            for (int c = 0; c < 4; ++c) acc[mt][nt][c] = 0.f;

    const int rA = lane & 15, cAs = lane >> 4;
    const int rB = ((lane >> 4) << 3) + (lane & 7);
    const int cBs = (lane >> 3) & 1;
    const int fr = lane >> 2, fc = (lane & 3) * 4;   // fp8 fragment addressing

    auto stage_load = [&](int ch) {
        const uint32_t stg = SB + (uint32_t)(ch % 3) * B_STAGE;
#pragma unroll
        for (int it = 0; it < 8; ++it) {
            const int v = it * 256 + tid;     // 0..2047
            uint32_t dst;
            const char* src;
            if (v < 512) {                    // NpH bf16 [r][64B], swizzled
                const int r = v >> 2, c = v & 3;
                dst = stg + S_NH + (uint32_t)(r * 64 + ((c ^ ((r >> 1) & 3)) << 4));
                src = (const char*)g_NpH + (size_t)(pb * 128 + r) * 2048 + ch * 64 + c * 16;
            } else if (v < 768) {             // Npq fp8 [r][32B]
                const int g = v - 512, r = g >> 1, h = g & 1;
                dst = stg + S_NQ + (uint32_t)(r * 32 + h * 16);
                src = (const char*)g_Npq + (size_t)(pb * 128 + r) * 1024 + ch * 32 + h * 16;
            } else if (v < 1024) {            // Npql
                const int g = v - 768, r = g >> 1, h = g & 1;
                dst = stg + S_NQL + (uint32_t)(r * 32 + h * 16);
                src = (const char*)g_Npql + (size_t)(pb * 128 + r) * 1024 + ch * 32 + h * 16;
            } else if (v < 1536) {            // gWh bf16
                const int g = v - 1024, r = g >> 2, c = g & 3;
                dst = stg + S_GH + (uint32_t)(r * 64 + ((c ^ ((r >> 1) & 3)) << 4));
                src = (const char*)g_gWh + (size_t)r * 2048 + ch * 64 + c * 16;
            } else if (v < 1792) {            // gWq
                const int g = v - 1536, r = g >> 1, h = g & 1;
                dst = stg + S_GQ + (uint32_t)(r * 32 + h * 16);
                src = (const char*)g_gWq + (size_t)r * 1024 + ch * 32 + h * 16;
            } else {                          // gWql
                const int g = v - 1792, r = g >> 1, h = g & 1;
                dst = stg + S_GQL + (uint32_t)(r * 32 + h * 16);
                src = (const char*)g_gWql + (size_t)r * 1024 + ch * 32 + h * 16;
            }
            cp16(dst, src);
        }
    };

    stage_load(0); cp_commit();
    stage_load(1); cp_commit();

    for (int ch = 0; ch < 32; ++ch) {
        if (ch < 31) cp_wait<1>(); else cp_wait<0>();
        __syncthreads();
        if (ch + 2 < 32) { stage_load(ch + 2); cp_commit(); }

        const uint32_t stg = SB + (uint32_t)(ch % 3) * B_STAGE;

        // ---- main hi*hi (bf16, 2 k-steps of 16) ----
#pragma unroll
        for (int ks = 0; ks < 2; ++ks) {
            uint32_t ah[2][4];
#pragma unroll
            for (int mt = 0; mt < 2; ++mt) {
                const int r = mp + mt * 16 + rA;
                const int c = ks * 2 + cAs;
                ldmx4(ah[mt], stg + S_NH
                      + (uint32_t)(r * 64 + ((c ^ ((r >> 1) & 3)) << 4)));
            }
#pragma unroll
            for (int n4 = 0; n4 < 4; ++n4) {
                uint32_t bh[4];
                const int r = ob + n4 * 16 + rB;
                const int c = ks * 2 + cBs;
                ldmx4(bh, stg + S_GH
                      + (uint32_t)(r * 64 + ((c ^ ((r >> 1) & 3)) << 4)));
#pragma unroll
                for (int half = 0; half < 2; ++half) {
                    const int nt = n4 * 2 + half;
#pragma unroll
                    for (int mt = 0; mt < 2; ++mt)
                        mma16816(acc[mt][nt], ah[mt], bh + half * 2);
                }
            }
        }

        // ---- cross terms (fp8 e4m3, K=32 per mma, unit product scale) ----
#pragma unroll
        for (int mt = 0; mt < 2; ++mt) {
            const int r0 = mp + mt * 16 + fr;
            uint32_t aq[4], aql[4];
            aq[0]  = lds32(stg + S_NQ  + (uint32_t)(r0 * 32 + fc));
            aq[1]  = lds32(stg + S_NQ  + (uint32_t)((r0 + 8) * 32 + fc));
            aq[2]  = lds32(stg + S_NQ  + (uint32_t)(r0 * 32 + fc + 16));
            aq[3]  = lds32(stg + S_NQ  + (uint32_t)((r0 + 8) * 32 + fc + 16));
            aql[0] = lds32(stg + S_NQL + (uint32_t)(r0 * 32 + fc));
            aql[1] = lds32(stg + S_NQL + (uint32_t)((r0 + 8) * 32 + fc));
            aql[2] = lds32(stg + S_NQL + (uint32_t)(r0 * 32 + fc + 16));
            aql[3] = lds32(stg + S_NQL + (uint32_t)((r0 + 8) * 32 + fc + 16));
#pragma unroll
            for (int nt = 0; nt < 8; ++nt) {
                const int rb = ob + nt * 8 + fr;
                uint32_t bql[2], bq[2];
                bql[0] = lds32(stg + S_GQL + (uint32_t)(rb * 32 + fc));
                bql[1] = lds32(stg + S_GQL + (uint32_t)(rb * 32 + fc + 16));
                bq[0]  = lds32(stg + S_GQ  + (uint32_t)(rb * 32 + fc));
                bq[1]  = lds32(stg + S_GQ  + (uint32_t)(rb * 32 + fc + 16));
                qmma16832(acc[mt][nt], aq, bql);   // (np*2^-7) * (gWl*2^7)
                qmma16832(acc[mt][nt], aql, bq);   // (npl*2^2) * (gW*2^-2)
            }
        }
    }

    // ---------------- epilogue ----------------
#pragma unroll
    for (int nt = 0; nt < 8; ++nt) {
        const int o0 = ob + nt * 8 + 2 * (lane & 3);
        const float cb0 = g_cb[o0], cb1 = g_cb[o0 + 1];
#pragma unroll
        for (int mt = 0; mt < 2; ++mt) {
            const int r0 = mp + mt * 16 + (lane >> 2);
            const size_t pair0 = (size_t)pb * 128 + r0;
            float2 v0, v1;
            v0.x = acc[mt][nt][0] + cb0;
            v0.y = acc[mt][nt][1] + cb1;
            v1.x = acc[mt][nt][2] + cb0;
            v1.y = acc[mt][nt][3] + cb1;
            *(float2*)&out[pair0 * NOUT + o0] = v0;
            *(float2*)&out[(pair0 + 8) * NOUT + o0] = v1;
        }
    }
}

// ---------------------------------------------------------------------------
extern "C" void kernel_launch(void* const* d_in, const int* in_sizes, int n_in,
                              void* d_out, int out_size) {
    const float* x_down   = (const float*)d_in[0];
    const float* x_down_w = (const float*)d_in[1];
    const float* gamma    = (const float*)d_in[2];
    const float* beta     = (const float*)d_in[3];
    const float* W        = (const float*)d_in[4];
    const float* b        = (const float*)d_in[5];
    float* out = (float*)d_out;

    cudaFuncSetAttribute(coevol_g1_kernel,
                         cudaFuncAttributeMaxDynamicSharedMemorySize, SMEM_A_TOTAL);
    cudaFuncSetAttribute(coevol_g2_kernel,
                         cudaFuncAttributeMaxDynamicSharedMemorySize, SMEM_B_TOTAL);

    prep_all<<<2176, 256>>>(x_down, x_down_w, gamma, beta, W, b);

    dim3 grid1(SEQ_L / 4, SEQ_L / 4);  // 64 x 64
    coevol_g1_kernel<<<grid1, 256, SMEM_A_TOTAL>>>();

    coevol_g2_kernel<<<512, 256, SMEM_B_TOTAL>>>(out);
}

// round 11
// speedup vs baseline: 1.1511x; 1.1511x over previous
#include <cuda_runtime.h>
#include <cuda_fp16.h>
#include <cstdint>

#define LN_EPS 1e-5f
#define SEQ_L  256
#define KDIM   1024
#define NOUT   128
#define SC     2048.f
#define INV_SC 4.8828125e-4f   // 1/2048

// ---------------- global scratch (no allocs allowed) ----------------
// fp16 splits: hi = fp16(x), lo = fp16((x - hi) * 2048)
__device__ __align__(16) __half g_Ah[128 * 8192];  // x_down   hi [n][ij]
__device__ __align__(16) __half g_Al[128 * 8192];  // lo * 2048
__device__ __align__(16) __half g_Bh[128 * 8192];  // x_down_w hi [n][lm]
__device__ __align__(16) __half g_Bl[128 * 8192];
__device__ __align__(16) __half g_gWh[NOUT * KDIM];  // gamma*W hi [o][k]
__device__ __align__(16) __half g_gWl[NOUT * KDIM];  // lo * 2048
__device__ float g_cb[NOUT];
// normalized pair fp16 split, [pair = i*256+l][k]
__device__ __align__(16) __half g_NpH[65536 * KDIM];
__device__ __align__(16) __half g_NpL[65536 * KDIM];  // lo * 2048

// ---------------- kernel A smem: 2 stages x (4 bufs x [32 n x 272 B]) ------
#define A_STAGE   34816
#define A_AH 0
#define A_AL 8704
#define A_BH 17408
#define A_BL 26112
#define OFF_NPH 0
#define OFF_NPL 33024
#define SMEM_A_TOTAL 69632

// ---------------- kernel B smem: 3 stages x (4 bufs x [128 r x 128 B]) -----
#define B_STAGE   32768
#define B_N 0
#define B_G 16384
#define SMEM_B_TOTAL 98304

__device__ __forceinline__ uint32_t smem_u32(const void* p) {
    uint32_t a;
    asm("{ .reg .u64 t; cvta.to.shared.u64 t, %1; cvt.u32.u64 %0, t; }"
        : "=r"(a) : "l"(p));
    return a;
}
__device__ __forceinline__ void cp16(uint32_t dst, const void* src) {
    asm volatile("cp.async.cg.shared.global [%0], [%1], 16;"
                 :: "r"(dst), "l"(src) : "memory");
}
__device__ __forceinline__ void cp_commit() {
    asm volatile("cp.async.commit_group;" ::: "memory");
}
template <int N> __device__ __forceinline__ void cp_wait() {
    asm volatile("cp.async.wait_group %0;" :: "n"(N) : "memory");
}
__device__ __forceinline__ void ldmx4t(uint32_t* r, uint32_t addr) {
    asm volatile("ldmatrix.sync.aligned.m8n8.x4.trans.shared.b16 {%0,%1,%2,%3}, [%4];"
                 : "=r"(r[0]), "=r"(r[1]), "=r"(r[2]), "=r"(r[3]) : "r"(addr));
}
__device__ __forceinline__ void ldmx2t(uint32_t* r, uint32_t addr) {
    asm volatile("ldmatrix.sync.aligned.m8n8.x2.trans.shared.b16 {%0,%1}, [%2];"
                 : "=r"(r[0]), "=r"(r[1]) : "r"(addr));
}
__device__ __forceinline__ void ldmx4(uint32_t* r, uint32_t addr) {
    asm volatile("ldmatrix.sync.aligned.m8n8.x4.shared.b16 {%0,%1,%2,%3}, [%4];"
                 : "=r"(r[0]), "=r"(r[1]), "=r"(r[2]), "=r"(r[3]) : "r"(addr));
}
// fp16 inputs, fp32 accumulate (main product)
__device__ __forceinline__ void mma_f32(float* c, const uint32_t* a, const uint32_t* b) {
    asm volatile(
        "mma.sync.aligned.m16n8k16.row.col.f32.f16.f16.f32 "
        "{%0,%1,%2,%3}, {%4,%5,%6,%7}, {%8,%9}, {%0,%1,%2,%3};"
        : "+f"(c[0]), "+f"(c[1]), "+f"(c[2]), "+f"(c[3])
        : "r"(a[0]), "r"(a[1]), "r"(a[2]), "r"(a[3]), "r"(b[0]), "r"(b[1]));
}
// fp16 inputs, fp16 accumulate (correction products; pre-scaled operands)
__device__ __forceinline__ void mma_f16(uint32_t* c, const uint32_t* a, const uint32_t* b) {
    asm volatile(
        "mma.sync.aligned.m16n8k16.row.col.f16.f16.f16.f16 "
        "{%0,%1}, {%2,%3,%4,%5}, {%6,%7}, {%0,%1};"
        : "+r"(c[0]), "+r"(c[1])
        : "r"(a[0]), "r"(a[1]), "r"(a[2]), "r"(a[3]), "r"(b[0]), "r"(b[1]));
}
__device__ __forceinline__ float h2lo(uint32_t v) {
    __half2 h = *(__half2*)&v;
    return __half2float(__low2half(h));
}
__device__ __forceinline__ float h2hi(uint32_t v) {
    __half2 h = *(__half2*)&v;
    return __half2float(__high2half(h));
}

// ---------------- prep: fp32 -> fp16 hi/lo (lo pre-scaled x2048) ----------
__global__ void prep_all(const float* __restrict__ A, const float* __restrict__ B,
                         const float* __restrict__ gamma, const float* __restrict__ beta,
                         const float* __restrict__ W, const float* __restrict__ b) {
    if (blockIdx.x < 2048) {
        const unsigned v = blockIdx.x * 256 + threadIdx.x;  // float4 index
        const float4* src;
        __half *dh, *dl;
        unsigned i;
        if (v < 262144) { src = (const float4*)A; i = v; dh = g_Ah; dl = g_Al; }
        else            { src = (const float4*)B; i = v - 262144; dh = g_Bh; dl = g_Bl; }
        const float4 x = src[i];
        __half2 h01 = __floats2half2_rn(x.x, x.y);
        __half2 h23 = __floats2half2_rn(x.z, x.w);
        __half2 l01 = __floats2half2_rn((x.x - __half2float(__low2half(h01))) * SC,
                                        (x.y - __half2float(__high2half(h01))) * SC);
        __half2 l23 = __floats2half2_rn((x.z - __half2float(__low2half(h23))) * SC,
                                        (x.w - __half2float(__high2half(h23))) * SC);
        ((uint2*)dh)[i] = make_uint2(*(uint32_t*)&h01, *(uint32_t*)&h23);
        ((uint2*)dl)[i] = make_uint2(*(uint32_t*)&l01, *(uint32_t*)&l23);
    } else {
        const int o = blockIdx.x - 2048;
        const int t = threadIdx.x;
        float s = 0.f;
        for (int k = t; k < KDIM; k += 256) {
            const float wv = W[o * KDIM + k];
            const float gv = gamma[k] * wv;
            const __half h = __float2half_rn(gv);
            g_gWh[o * KDIM + k] = h;
            g_gWl[o * KDIM + k] = __float2half_rn((gv - __half2float(h)) * SC);
            s += beta[k] * wv;
        }
        __shared__ float red[256];
        red[t] = s;
        __syncthreads();
        for (int st = 128; st > 0; st >>= 1) {
            if (t < st) red[t] += red[t + st];
            __syncthreads();
        }
        if (t == 0) g_cb[o] = b[o] + red[0];
    }
}

// ---------------- kernel A: GEMM1 + LN -> g_Np (2-stage cp.async) ----------
__global__ __launch_bounds__(256, 2)
void coevol_g1_kernel() {
    extern __shared__ char sm[];
    const uint32_t SB = smem_u32(sm);

    const int tid = threadIdx.x;
    const int lane = tid & 31, w = tid >> 5;
    const int bx = blockIdx.x, by = blockIdx.y;

    const int mbase = (w & 3) * 32;
    const int nbase = (w >> 2) * 64;
    float acc[2][8][4];
    uint32_t acc16[2][8][2];
#pragma unroll
    for (int mt = 0; mt < 2; ++mt)
#pragma unroll
        for (int nt = 0; nt < 8; ++nt) {
#pragma unroll
            for (int c = 0; c < 4; ++c) acc[mt][nt][c] = 0.f;
            acc16[mt][nt][0] = 0u;
            acc16[mt][nt][1] = 0u;
        }

    const int g4 = lane >> 3;
    const int grow = lane & 7;
    const int kadd4 = (g4 >> 1) * 8, madd4 = (g4 & 1) * 8;
    const int kadd2 = (g4 & 1) * 8;

    auto stage_load = [&](int ch) {
        const uint32_t stg = SB + (uint32_t)(ch & 1) * A_STAGE;
#pragma unroll
        for (int it = 0; it < 8; ++it) {
            const int v = it * 256 + tid;
            const int buf = v >> 9;
            const int rem = v & 511;
            const int r = rem >> 4, c = rem & 15;
            const size_t srow = (size_t)(ch * 32 + r) * 16384;  // 8192 fp16/row
            const uint32_t dst = stg + (uint32_t)buf * 8704u
                               + (uint32_t)r * 272u + (uint32_t)c * 16u;
            const char* src;
            if (buf == 0)      src = (const char*)g_Ah + srow + bx * 256 + c * 16;
            else if (buf == 1) src = (const char*)g_Al + srow + bx * 256 + c * 16;
            else if (buf == 2) src = (const char*)g_Bh + srow + by * 256 + c * 16;
            else               src = (const char*)g_Bl + srow + by * 256 + c * 16;
            cp16(dst, src);
        }
    };

    stage_load(0);
    cp_commit();

    for (int ch = 0; ch < 4; ++ch) {
        cp_wait<0>();
        __syncthreads();
        if (ch < 3) { stage_load(ch + 1); cp_commit(); }

        const uint32_t stg = SB + (uint32_t)(ch & 1) * A_STAGE;
#pragma unroll
        for (int ks = 0; ks < 2; ++ks) {
            uint32_t ah[2][4], al[2][4];
#pragma unroll
            for (int mt = 0; mt < 2; ++mt) {
                const uint32_t aoff = (uint32_t)(ks * 16 + kadd4 + grow) * 272u
                                    + (uint32_t)(mbase + mt * 16 + madd4) * 2u;
                ldmx4t(ah[mt], stg + A_AH + aoff);
                ldmx4t(al[mt], stg + A_AL + aoff);
            }
#pragma unroll
            for (int nt = 0; nt < 8; ++nt) {
                uint32_t bh[2], bl[2];
                const uint32_t boff = (uint32_t)(ks * 16 + kadd2 + grow) * 272u
                                    + (uint32_t)(nbase + nt * 8) * 2u;
                ldmx2t(bh, stg + A_BH + boff);
                ldmx2t(bl, stg + A_BL + boff);
#pragma unroll
                for (int mt = 0; mt < 2; ++mt) {
                    mma_f32(acc[mt][nt], ah[mt], bh);      // hi*hi  (f32 acc)
                    mma_f16(acc16[mt][nt], ah[mt], bl);    // hi*lo' (f16 acc)
                    mma_f16(acc16[mt][nt], al[mt], bh);    // lo'*hi (f16 acc)
                }
            }
        }
    }
    __syncthreads();  // stage smem reuse for Np staging

    // merge scaled f16 correction into f32 accumulators
#pragma unroll
    for (int mt = 0; mt < 2; ++mt)
#pragma unroll
        for (int nt = 0; nt < 8; ++nt) {
            acc[mt][nt][0] += h2lo(acc16[mt][nt][0]) * INV_SC;
            acc[mt][nt][1] += h2hi(acc16[mt][nt][0]) * INV_SC;
            acc[mt][nt][2] += h2lo(acc16[mt][nt][1]) * INV_SC;
            acc[mt][nt][3] += h2hi(acc16[mt][nt][1]) * INV_SC;
        }

    // ---------------- LayerNorm (warp-local) -> Np smem fp16 hi/lo ----------
    const int i_loc = w & 3;
#pragma unroll
    for (int lb = 0; lb < 2; ++lb) {
        const int l_loc = (w >> 2) * 2 + lb;
        float sum = 0.f, sq = 0.f;
#pragma unroll
        for (int mt = 0; mt < 2; ++mt)
#pragma unroll
            for (int nt4 = 0; nt4 < 4; ++nt4)
#pragma unroll
                for (int c = 0; c < 4; ++c) {
                    const float v = acc[mt][lb * 4 + nt4][c];
                    sum += v;
                    sq = fmaf(v, v, sq);
                }
#pragma unroll
        for (int off = 16; off >= 1; off >>= 1) {
            sum += __shfl_xor_sync(0xffffffffu, sum, off);
            sq  += __shfl_xor_sync(0xffffffffu, sq, off);
        }
        const float mean = sum * (1.f / KDIM);
        const float var  = sq * (1.f / KDIM) - mean * mean;
        const float rstd = rsqrtf(var + LN_EPS);
        const int p = i_loc * 4 + l_loc;
#pragma unroll
        for (int mt = 0; mt < 2; ++mt)
#pragma unroll
            for (int nt4 = 0; nt4 < 4; ++nt4)
#pragma unroll
                for (int cp = 0; cp < 2; ++cp) {
                    const float f0 = (acc[mt][lb * 4 + nt4][cp * 2 + 0] - mean) * rstd;
                    const float f1 = (acc[mt][lb * 4 + nt4][cp * 2 + 1] - mean) * rstd;
                    __half2 h2 = __floats2half2_rn(f0, f1);
                    __half2 l2 = __floats2half2_rn(
                        (f0 - __half2float(__low2half(h2))) * SC,
                        (f1 - __half2float(__high2half(h2))) * SC);
                    const int j  = mt * 16 + (lane >> 2) + cp * 8;
                    const int mc = nt4 * 4 + (lane & 3);
                    const int idx = p * 516 + j * 16 + (mc ^ ((j & 3) << 2));
                    *(uint32_t*)(sm + OFF_NPH + idx * 4) = *(uint32_t*)&h2;
                    *(uint32_t*)(sm + OFF_NPL + idx * 4) = *(uint32_t*)&l2;
                }
    }
    __syncthreads();

    // ---------------- copy Np smem -> global (coalesced) ----------
#pragma unroll
    for (int it = 0; it < 16; ++it) {
        const int v = it * 256 + tid;          // 0..4095
        const int arr = v >> 11;
        const int rem = v & 2047;
        const int p = rem >> 7;
        const int c4 = rem & 127;
        const int wb = c4 * 4;
        const int j = wb >> 4, mc = wb & 15;
        const int sidx = p * 516 + j * 16 + (mc ^ ((j & 3) << 2));
        const uint32_t* s = (const uint32_t*)(sm + (arr ? OFF_NPL : OFF_NPH)) + sidx;
        uint4 val = make_uint4(s[0], s[1], s[2], s[3]);
        const int gi = bx * 4 + (p >> 2);
        const int gl = by * 4 + (p & 3);
        const size_t pair = (size_t)gi * SEQ_L + gl;
        uint4* dst = (uint4*)(arr ? g_NpL : g_NpH) + pair * 128 + c4;
        *dst = val;
    }
}

// ---------------- kernel B: out = Np . gW + cb (3-stage cp.async) ----------
// Grid 512: CTA = 128 pairs x 128 o, K = 1024 in 32 chunks of 32.
__global__ __launch_bounds__(256, 2)
void coevol_g2_kernel(float* __restrict__ out) {
    extern __shared__ char sm[];
    const uint32_t SB = smem_u32(sm);

    const int tid = threadIdx.x;
    const int lane = tid & 31, w = tid >> 5;
    const int pb = blockIdx.x;

    const int mp = (w & 3) * 32;
    const int ob = (w >> 2) * 64;

    float acc[2][8][4];
    uint32_t acc16[2][8][2];
#pragma unroll
    for (int mt = 0; mt < 2; ++mt)
#pragma unroll
        for (int nt = 0; nt < 8; ++nt) {
#pragma unroll
            for (int c = 0; c < 4; ++c) acc[mt][nt][c] = 0.f;
            acc16[mt][nt][0] = 0u;
            acc16[mt][nt][1] = 0u;
        }

    const int rA = lane & 15, cAs = lane >> 4;
    const int rB = ((lane >> 4) << 3) + (lane & 7);
    const int cBs = (lane >> 3) & 1;

    // stage load: 8 cp16/thread. row layout: c<4 hi, c>=4 lo; xor-swizzled.
    auto stage_load = [&](int ch) {
        const uint32_t stg = SB + (uint32_t)(ch % 3) * B_STAGE;
#pragma unroll
        for (int it = 0; it < 8; ++it) {
            const int v = it * 256 + tid;
            const int buf = v >> 10;          // 0 = Np, 1 = gW
            const int rem = v & 1023;
            const int r = rem >> 3, c = rem & 7;
            const uint32_t dst = stg + (uint32_t)buf * 16384u
                               + (uint32_t)r * 128u
                               + (uint32_t)((c ^ (r & 7)) << 4);
            const char* src;
            if (buf == 0) {
                const size_t row = (size_t)(pb * 128 + r) * 2048;
                src = (c < 4)
                    ? (const char*)g_NpH + row + ch * 64 + c * 16
                    : (const char*)g_NpL + row + ch * 64 + (c - 4) * 16;
            } else {
                const size_t row = (size_t)r * 2048;
                src = (c < 4)
                    ? (const char*)g_gWh + row + ch * 64 + c * 16
                    : (const char*)g_gWl + row + ch * 64 + (c - 4) * 16;
            }
            cp16(dst, src);
        }
    };

    stage_load(0); cp_commit();
    stage_load(1); cp_commit();

    for (int ch = 0; ch < 32; ++ch) {
        if (ch < 31) cp_wait<1>(); else cp_wait<0>();
        __syncthreads();
        if (ch + 2 < 32) { stage_load(ch + 2); cp_commit(); }

        const uint32_t stg = SB + (uint32_t)(ch % 3) * B_STAGE;
#pragma unroll
        for (int ks = 0; ks < 2; ++ks) {
            const int cc = ks * 2;
            uint32_t ah[2][4], al[2][4];
#pragma unroll
            for (int mt = 0; mt < 2; ++mt) {
                const int r = mp + mt * 16 + rA;
                const int ch_ = cc + cAs;          // hi col 0..3
                const uint32_t base = stg + B_N + (uint32_t)(r * 128);
                ldmx4(ah[mt], base + (uint32_t)(((ch_) ^ (r & 7)) << 4));
                ldmx4(al[mt], base + (uint32_t)(((ch_ + 4) ^ (r & 7)) << 4));
            }
#pragma unroll
            for (int n4 = 0; n4 < 4; ++n4) {
                uint32_t bh[4], bl[4];
                const int r = ob + n4 * 16 + rB;
                const int ch_ = cc + cBs;
                const uint32_t base = stg + B_G + (uint32_t)(r * 128);
                ldmx4(bh, base + (uint32_t)(((ch_) ^ (r & 7)) << 4));
                ldmx4(bl, base + (uint32_t)(((ch_ + 4) ^ (r & 7)) << 4));
#pragma unroll
                for (int half = 0; half < 2; ++half) {
                    const int nt = n4 * 2 + half;
#pragma unroll
                    for (int mt = 0; mt < 2; ++mt) {
                        mma_f32(acc[mt][nt], ah[mt], bh + half * 2);
                        mma_f16(acc16[mt][nt], ah[mt], bl + half * 2);
                        mma_f16(acc16[mt][nt], al[mt], bh + half * 2);
                    }
                }
            }
        }
    }

    // ---------------- epilogue (merge f16 correction, /2048) ----------------
#pragma unroll
    for (int nt = 0; nt < 8; ++nt) {
        const int o0 = ob + nt * 8 + 2 * (lane & 3);
        const float cb0 = g_cb[o0], cb1 = g_cb[o0 + 1];
#pragma unroll
        for (int mt = 0; mt < 2; ++mt) {
            const int r0 = mp + mt * 16 + (lane >> 2);
            const size_t pair0 = (size_t)pb * 128 + r0;
            float2 v0, v1;
            v0.x = acc[mt][nt][0] + h2lo(acc16[mt][nt][0]) * INV_SC + cb0;
            v0.y = acc[mt][nt][1] + h2hi(acc16[mt][nt][0]) * INV_SC + cb1;
            v1.x = acc[mt][nt][2] + h2lo(acc16[mt][nt][1]) * INV_SC + cb0;
            v1.y = acc[mt][nt][3] + h2hi(acc16[mt][nt][1]) * INV_SC + cb1;
            *(float2*)&out[pair0 * NOUT + o0] = v0;
            *(float2*)&out[(pair0 + 8) * NOUT + o0] = v1;
        }
    }
}

// ---------------------------------------------------------------------------
extern "C" void kernel_launch(void* const* d_in, const int* in_sizes, int n_in,
                              void* d_out, int out_size) {
    const float* x_down   = (const float*)d_in[0];
    const float* x_down_w = (const float*)d_in[1];
    const float* gamma    = (const float*)d_in[2];
    const float* beta     = (const float*)d_in[3];
    const float* W        = (const float*)d_in[4];
    const float* b        = (const float*)d_in[5];
    float* out = (float*)d_out;

    cudaFuncSetAttribute(coevol_g1_kernel,
                         cudaFuncAttributeMaxDynamicSharedMemorySize, SMEM_A_TOTAL);
    cudaFuncSetAttribute(coevol_g2_kernel,
                         cudaFuncAttributeMaxDynamicSharedMemorySize, SMEM_B_TOTAL);

    prep_all<<<2176, 256>>>(x_down, x_down_w, gamma, beta, W, b);

    dim3 grid1(SEQ_L / 4, SEQ_L / 4);  // 64 x 64
    coevol_g1_kernel<<<grid1, 256, SMEM_A_TOTAL>>>();

    coevol_g2_kernel<<<512, 256, SMEM_B_TOTAL>>>(out);
}

// round 12
// speedup vs baseline: 1.7541x; 1.5238x over previous
#include <cuda_runtime.h>
#include <cuda_fp16.h>
#include <cstdint>

#define LN_EPS 1e-5f
#define SEQ_L  256
#define KDIM   1024
#define NOUT   128

// ---------------- global scratch (no allocs allowed) ----------------
// fp16 split: hi = fp16(x), lo = fp16(x - hi)  (unscaled; ~2^-12, fp16-normal)
__device__ __align__(16) __half g_Ah[128 * 8192];  // x_down   hi [n][ij]
__device__ __align__(16) __half g_Al[128 * 8192];  // x_down   lo
__device__ __align__(16) __half g_Bh[128 * 8192];  // x_down_w hi [n][lm]
__device__ __align__(16) __half g_gWh[NOUT * KDIM];  // gamma*W hi [o][k]
__device__ float g_cb[NOUT];
// normalized pair fp16 split, [pair = i*256+l][k]
__device__ __align__(16) __half g_NpH[65536 * KDIM];
__device__ __align__(16) __half g_NpL[65536 * KDIM];

// ---------------- kernel A smem: 2 stages x (3 bufs x [32 n x 272 B]) ------
#define A_STAGE   26112
#define A_AH 0
#define A_AL 8704
#define A_BH 17408
#define OFF_NPH 0
#define OFF_NPL 33024
#define SMEM_A_TOTAL 66048

// ---------------- kernel B smem: 3 stages x (Np 16KB + gW 8KB) -------------
// Np row = 128 B (hi c0-3, lo c4-7, swizzle c^(r&7)); gW row = 64 B (swizzle
// c^((r>>1)&3)).
#define S_N 0
#define S_G 16384
#define B_STAGE   24576
#define SMEM_B_TOTAL 73728

__device__ __forceinline__ uint32_t smem_u32(const void* p) {
    uint32_t a;
    asm("{ .reg .u64 t; cvta.to.shared.u64 t, %1; cvt.u32.u64 %0, t; }"
        : "=r"(a) : "l"(p));
    return a;
}
__device__ __forceinline__ void cp16(uint32_t dst, const void* src) {
    asm volatile("cp.async.cg.shared.global [%0], [%1], 16;"
                 :: "r"(dst), "l"(src) : "memory");
}
__device__ __forceinline__ void cp_commit() {
    asm volatile("cp.async.commit_group;" ::: "memory");
}
template <int N> __device__ __forceinline__ void cp_wait() {
    asm volatile("cp.async.wait_group %0;" :: "n"(N) : "memory");
}
__device__ __forceinline__ void ldmx4t(uint32_t* r, uint32_t addr) {
    asm volatile("ldmatrix.sync.aligned.m8n8.x4.trans.shared.b16 {%0,%1,%2,%3}, [%4];"
                 : "=r"(r[0]), "=r"(r[1]), "=r"(r[2]), "=r"(r[3]) : "r"(addr));
}
__device__ __forceinline__ void ldmx2t(uint32_t* r, uint32_t addr) {
    asm volatile("ldmatrix.sync.aligned.m8n8.x2.trans.shared.b16 {%0,%1}, [%2];"
                 : "=r"(r[0]), "=r"(r[1]) : "r"(addr));
}
__device__ __forceinline__ void ldmx4(uint32_t* r, uint32_t addr) {
    asm volatile("ldmatrix.sync.aligned.m8n8.x4.shared.b16 {%0,%1,%2,%3}, [%4];"
                 : "=r"(r[0]), "=r"(r[1]), "=r"(r[2]), "=r"(r[3]) : "r"(addr));
}
// fp16 inputs, fp32 accumulate
__device__ __forceinline__ void mma_f32(float* c, const uint32_t* a, const uint32_t* b) {
    asm volatile(
        "mma.sync.aligned.m16n8k16.row.col.f32.f16.f16.f32 "
        "{%0,%1,%2,%3}, {%4,%5,%6,%7}, {%8,%9}, {%0,%1,%2,%3};"
        : "+f"(c[0]), "+f"(c[1]), "+f"(c[2]), "+f"(c[3])
        : "r"(a[0]), "r"(a[1]), "r"(a[2]), "r"(a[3]), "r"(b[0]), "r"(b[1]));
}

// ---------------- prep: fp32 -> fp16 hi(/lo for A only, gW hi only) --------
__global__ void prep_all(const float* __restrict__ A, const float* __restrict__ B,
                         const float* __restrict__ gamma, const float* __restrict__ beta,
                         const float* __restrict__ W, const float* __restrict__ b) {
    if (blockIdx.x < 2048) {
        const unsigned v = blockIdx.x * 256 + threadIdx.x;  // float4 index
        if (v < 262144) {                 // x_down: hi + lo
            const float4 x = ((const float4*)A)[v];
            __half2 h01 = __floats2half2_rn(x.x, x.y);
            __half2 h23 = __floats2half2_rn(x.z, x.w);
            __half2 l01 = __floats2half2_rn(x.x - __half2float(__low2half(h01)),
                                            x.y - __half2float(__high2half(h01)));
            __half2 l23 = __floats2half2_rn(x.z - __half2float(__low2half(h23)),
                                            x.w - __half2float(__high2half(h23)));
            ((uint2*)g_Ah)[v] = make_uint2(*(uint32_t*)&h01, *(uint32_t*)&h23);
            ((uint2*)g_Al)[v] = make_uint2(*(uint32_t*)&l01, *(uint32_t*)&l23);
        } else {                          // x_down_w: hi only
            const unsigned i = v - 262144;
            const float4 x = ((const float4*)B)[i];
            __half2 h01 = __floats2half2_rn(x.x, x.y);
            __half2 h23 = __floats2half2_rn(x.z, x.w);
            ((uint2*)g_Bh)[i] = make_uint2(*(uint32_t*)&h01, *(uint32_t*)&h23);
        }
    } else {
        const int o = blockIdx.x - 2048;
        const int t = threadIdx.x;
        float s = 0.f;
        for (int k = t; k < KDIM; k += 256) {
            const float wv = W[o * KDIM + k];
            g_gWh[o * KDIM + k] = __float2half_rn(gamma[k] * wv);
            s += beta[k] * wv;
        }
        __shared__ float red[256];
        red[t] = s;
        __syncthreads();
        for (int st = 128; st > 0; st >>= 1) {
            if (t < st) red[t] += red[t + st];
            __syncthreads();
        }
        if (t == 0) g_cb[o] = b[o] + red[0];
    }
}

// ---------------- kernel A: GEMM1 + LN -> g_Np (2-stage cp.async) ----------
// pair = Ah.Bh + Al.Bh  (dropped Ah.Bl ~ 2^-12 rel)
__global__ __launch_bounds__(256, 2)
void coevol_g1_kernel() {
    extern __shared__ char sm[];
    const uint32_t SB = smem_u32(sm);

    const int tid = threadIdx.x;
    const int lane = tid & 31, w = tid >> 5;
    const int bx = blockIdx.x, by = blockIdx.y;

    const int mbase = (w & 3) * 32;
    const int nbase = (w >> 2) * 64;
    float acc[2][8][4];
#pragma unroll
    for (int mt = 0; mt < 2; ++mt)
#pragma unroll
        for (int nt = 0; nt < 8; ++nt)
#pragma unroll
            for (int c = 0; c < 4; ++c) acc[mt][nt][c] = 0.f;

    const int g4 = lane >> 3;
    const int grow = lane & 7;
    const int kadd4 = (g4 >> 1) * 8, madd4 = (g4 & 1) * 8;
    const int kadd2 = (g4 & 1) * 8;

    // staging: 6 cp16/thread/stage. v: buf = v>>9 (AH,AL,BH); r=(v&511)>>4; c=v&15
    auto stage_load = [&](int ch) {
        const uint32_t stg = SB + (uint32_t)(ch & 1) * A_STAGE;
#pragma unroll
        for (int it = 0; it < 6; ++it) {
            const int v = it * 256 + tid;          // 0..1535
            const int buf = v >> 9;
            const int rem = v & 511;
            const int r = rem >> 4, c = rem & 15;
            const size_t srow = (size_t)(ch * 32 + r) * 16384;  // 8192 fp16/row
            const uint32_t dst = stg + (uint32_t)buf * 8704u
                               + (uint32_t)r * 272u + (uint32_t)c * 16u;
            const char* src;
            if (buf == 0)      src = (const char*)g_Ah + srow + bx * 256 + c * 16;
            else if (buf == 1) src = (const char*)g_Al + srow + bx * 256 + c * 16;
            else               src = (const char*)g_Bh + srow + by * 256 + c * 16;
            cp16(dst, src);
        }
    };

    stage_load(0);
    cp_commit();

    for (int ch = 0; ch < 4; ++ch) {
        cp_wait<0>();
        __syncthreads();
        if (ch < 3) { stage_load(ch + 1); cp_commit(); }

        const uint32_t stg = SB + (uint32_t)(ch & 1) * A_STAGE;
#pragma unroll
        for (int ks = 0; ks < 2; ++ks) {
            uint32_t ah[2][4], al[2][4];
#pragma unroll
            for (int mt = 0; mt < 2; ++mt) {
                const uint32_t aoff = (uint32_t)(ks * 16 + kadd4 + grow) * 272u
                                    + (uint32_t)(mbase + mt * 16 + madd4) * 2u;
                ldmx4t(ah[mt], stg + A_AH + aoff);
                ldmx4t(al[mt], stg + A_AL + aoff);
            }
#pragma unroll
            for (int nt = 0; nt < 8; ++nt) {
                uint32_t bh[2];
                const uint32_t boff = (uint32_t)(ks * 16 + kadd2 + grow) * 272u
                                    + (uint32_t)(nbase + nt * 8) * 2u;
                ldmx2t(bh, stg + A_BH + boff);
#pragma unroll
                for (int mt = 0; mt < 2; ++mt) {
                    mma_f32(acc[mt][nt], ah[mt], bh);   // hi*hi
                    mma_f32(acc[mt][nt], al[mt], bh);   // lo*hi
                }
            }
        }
    }
    __syncthreads();  // stage smem reuse for Np staging

    // ---------------- LayerNorm (warp-local) -> Np smem fp16 hi/lo ----------
    const int i_loc = w & 3;
#pragma unroll
    for (int lb = 0; lb < 2; ++lb) {
        const int l_loc = (w >> 2) * 2 + lb;
        float sum = 0.f, sq = 0.f;
#pragma unroll
        for (int mt = 0; mt < 2; ++mt)
#pragma unroll
            for (int nt4 = 0; nt4 < 4; ++nt4)
#pragma unroll
                for (int c = 0; c < 4; ++c) {
                    const float v = acc[mt][lb * 4 + nt4][c];
                    sum += v;
                    sq = fmaf(v, v, sq);
                }
#pragma unroll
        for (int off = 16; off >= 1; off >>= 1) {
            sum += __shfl_xor_sync(0xffffffffu, sum, off);
            sq  += __shfl_xor_sync(0xffffffffu, sq, off);
        }
        const float mean = sum * (1.f / KDIM);
        const float var  = sq * (1.f / KDIM) - mean * mean;
        const float rstd = rsqrtf(var + LN_EPS);
        const int p = i_loc * 4 + l_loc;
#pragma unroll
        for (int mt = 0; mt < 2; ++mt)
#pragma unroll
            for (int nt4 = 0; nt4 < 4; ++nt4)
#pragma unroll
                for (int cp = 0; cp < 2; ++cp) {
                    const float f0 = (acc[mt][lb * 4 + nt4][cp * 2 + 0] - mean) * rstd;
                    const float f1 = (acc[mt][lb * 4 + nt4][cp * 2 + 1] - mean) * rstd;
                    __half2 h2 = __floats2half2_rn(f0, f1);
                    __half2 l2 = __floats2half2_rn(
                        f0 - __half2float(__low2half(h2)),
                        f1 - __half2float(__high2half(h2)));
                    const int j  = mt * 16 + (lane >> 2) + cp * 8;
                    const int mc = nt4 * 4 + (lane & 3);
                    const int idx = p * 516 + j * 16 + (mc ^ ((j & 3) << 2));
                    *(uint32_t*)(sm + OFF_NPH + idx * 4) = *(uint32_t*)&h2;
                    *(uint32_t*)(sm + OFF_NPL + idx * 4) = *(uint32_t*)&l2;
                }
    }
    __syncthreads();

    // ---------------- copy Np smem -> global (coalesced) ----------
#pragma unroll
    for (int it = 0; it < 16; ++it) {
        const int v = it * 256 + tid;          // 0..4095
        const int arr = v >> 11;
        const int rem = v & 2047;
        const int p = rem >> 7;
        const int c4 = rem & 127;
        const int wb = c4 * 4;
        const int j = wb >> 4, mc = wb & 15;
        const int sidx = p * 516 + j * 16 + (mc ^ ((j & 3) << 2));
        const uint32_t* s = (const uint32_t*)(sm + (arr ? OFF_NPL : OFF_NPH)) + sidx;
        uint4 val = make_uint4(s[0], s[1], s[2], s[3]);
        const int gi = bx * 4 + (p >> 2);
        const int gl = by * 4 + (p & 3);
        const size_t pair = (size_t)gi * SEQ_L + gl;
        uint4* dst = (uint4*)(arr ? g_NpL : g_NpH) + pair * 128 + c4;
        *dst = val;
    }
}

// ---------------- kernel B: out = (NpH+NpL).gWh + cb (3-stage cp.async) ----
// Grid 512: CTA = 128 pairs x 128 o, K = 1024 in 32 chunks of 32.
__global__ __launch_bounds__(256, 2)
void coevol_g2_kernel(float* __restrict__ out) {
    extern __shared__ char sm[];
    const uint32_t SB = smem_u32(sm);

    const int tid = threadIdx.x;
    const int lane = tid & 31, w = tid >> 5;
    const int pb = blockIdx.x;

    const int mp = (w & 3) * 32;
    const int ob = (w >> 2) * 64;

    float acc[2][8][4];
#pragma unroll
    for (int mt = 0; mt < 2; ++mt)
#pragma unroll
        for (int nt = 0; nt < 8; ++nt)
#pragma unroll
            for (int c = 0; c < 4; ++c) acc[mt][nt][c] = 0.f;

    const int rA = lane & 15, cAs = lane >> 4;
    const int rB = ((lane >> 4) << 3) + (lane & 7);
    const int cBs = (lane >> 3) & 1;

    // stage load: 6 cp16/thread. Np rows 128B (hi c0-3 / lo c4-7); gW rows 64B.
    auto stage_load = [&](int ch) {
        const uint32_t stg = SB + (uint32_t)(ch % 3) * B_STAGE;
#pragma unroll
        for (int it = 0; it < 6; ++it) {
            const int v = it * 256 + tid;     // 0..1535
            uint32_t dst;
            const char* src;
            if (v < 1024) {                   // Np
                const int r = v >> 3, c = v & 7;
                dst = stg + S_N + (uint32_t)(r * 128 + ((c ^ (r & 7)) << 4));
                const size_t row = (size_t)(pb * 128 + r) * 2048;
                src = (c < 4)
                    ? (const char*)g_NpH + row + ch * 64 + c * 16
                    : (const char*)g_NpL + row + ch * 64 + (c - 4) * 16;
            } else {                          // gWh
                const int g = v - 1024;       // 0..511
                const int r = g >> 2, c = g & 3;
                dst = stg + S_G + (uint32_t)(r * 64 + ((c ^ ((r >> 1) & 3)) << 4));
                src = (const char*)g_gWh + (size_t)r * 2048 + ch * 64 + c * 16;
            }
            cp16(dst, src);
        }
    };

    stage_load(0); cp_commit();
    stage_load(1); cp_commit();

    for (int ch = 0; ch < 32; ++ch) {
        if (ch < 31) cp_wait<1>(); else cp_wait<0>();
        __syncthreads();
        if (ch + 2 < 32) { stage_load(ch + 2); cp_commit(); }

        const uint32_t stg = SB + (uint32_t)(ch % 3) * B_STAGE;
#pragma unroll
        for (int ks = 0; ks < 2; ++ks) {
            const int cc = ks * 2;
            uint32_t ah[2][4], al[2][4];
#pragma unroll
            for (int mt = 0; mt < 2; ++mt) {
                const int r = mp + mt * 16 + rA;
                const int c = cc + cAs;            // hi col 0..3
                const uint32_t base = stg + S_N + (uint32_t)(r * 128);
                ldmx4(ah[mt], base + (uint32_t)(((c) ^ (r & 7)) << 4));
                ldmx4(al[mt], base + (uint32_t)(((c + 4) ^ (r & 7)) << 4));
            }
#pragma unroll
            for (int n4 = 0; n4 < 4; ++n4) {
                uint32_t bh[4];
                const int r = ob + n4 * 16 + rB;
                const int c = cc + cBs;
                ldmx4(bh, stg + S_G
                      + (uint32_t)(r * 64 + ((c ^ ((r >> 1) & 3)) << 4)));
#pragma unroll
                for (int half = 0; half < 2; ++half) {
                    const int nt = n4 * 2 + half;
#pragma unroll
                    for (int mt = 0; mt < 2; ++mt) {
                        mma_f32(acc[mt][nt], ah[mt], bh + half * 2);   // hi*hi
                        mma_f32(acc[mt][nt], al[mt], bh + half * 2);   // lo*hi
                    }
                }
            }
        }
    }

    // ---------------- epilogue ----------------
#pragma unroll
    for (int nt = 0; nt < 8; ++nt) {
        const int o0 = ob + nt * 8 + 2 * (lane & 3);
        const float cb0 = g_cb[o0], cb1 = g_cb[o0 + 1];
#pragma unroll
        for (int mt = 0; mt < 2; ++mt) {
            const int r0 = mp + mt * 16 + (lane >> 2);
            const size_t pair0 = (size_t)pb * 128 + r0;
            float2 v0, v1;
            v0.x = acc[mt][nt][0] + cb0;
            v0.y = acc[mt][nt][1] + cb1;
            v1.x = acc[mt][nt][2] + cb0;
            v1.y = acc[mt][nt][3] + cb1;
            *(float2*)&out[pair0 * NOUT + o0] = v0;
            *(float2*)&out[(pair0 + 8) * NOUT + o0] = v1;
        }
    }
}

// ---------------------------------------------------------------------------
extern "C" void kernel_launch(void* const* d_in, const int* in_sizes, int n_in,
                              void* d_out, int out_size) {
    const float* x_down   = (const float*)d_in[0];
    const float* x_down_w = (const float*)d_in[1];
    const float* gamma    = (const float*)d_in[2];
    const float* beta     = (const float*)d_in[3];
    const float* W        = (const float*)d_in[4];
    const float* b        = (const float*)d_in[5];
    float* out = (float*)d_out;

    cudaFuncSetAttribute(coevol_g1_kernel,
                         cudaFuncAttributeMaxDynamicSharedMemorySize, SMEM_A_TOTAL);
    cudaFuncSetAttribute(coevol_g2_kernel,
                         cudaFuncAttributeMaxDynamicSharedMemorySize, SMEM_B_TOTAL);

    prep_all<<<2176, 256>>>(x_down, x_down_w, gamma, beta, W, b);

    dim3 grid1(SEQ_L / 4, SEQ_L / 4);  // 64 x 64
    coevol_g1_kernel<<<grid1, 256, SMEM_A_TOTAL>>>();

    coevol_g2_kernel<<<512, 256, SMEM_B_TOTAL>>>(out);
}

// round 13
// speedup vs baseline: 2.9660x; 1.6909x over previous
#include <cuda_runtime.h>
#include <cuda_fp16.h>
#include <cstdint>

#define LN_EPS 1e-5f
#define SEQ_L  256
#define KDIM   1024
#define NOUT   128

// ---------------- global scratch (no allocs allowed) ----------------
__device__ __align__(16) __half g_Ah[128 * 8192];   // fp16(x_down)   [n][ij]
__device__ __align__(16) __half g_Bh[128 * 8192];   // fp16(x_down_w) [n][lm]
__device__ __align__(16) __half g_gWh[NOUT * KDIM]; // fp16(gamma*W)  [o][k]
__device__ float g_cb[NOUT];
__device__ __align__(16) __half g_NpH[65536 * KDIM]; // fp16(LN(pair)) [pair][k]

// ---------------- kernel A smem: 2 stages x (2 bufs x [32 n x 272 B]) ------
#define A_STAGE   17408
#define A_AH 0
#define A_BH 8704
#define OFF_NPH 0
#define SMEM_A_TOTAL 34816

// ---------------- kernel B smem: 3 stages x (Np 8KB + gW 8KB) --------------
// rows 64 B, swizzle c ^ ((r>>1)&3), c in 16B units 0..3
#define S_N 0
#define S_G 8192
#define B_STAGE   16384
#define SMEM_B_TOTAL 49152

__device__ __forceinline__ uint32_t smem_u32(const void* p) {
    uint32_t a;
    asm("{ .reg .u64 t; cvta.to.shared.u64 t, %1; cvt.u32.u64 %0, t; }"
        : "=r"(a) : "l"(p));
    return a;
}
__device__ __forceinline__ void cp16(uint32_t dst, const void* src) {
    asm volatile("cp.async.cg.shared.global [%0], [%1], 16;"
                 :: "r"(dst), "l"(src) : "memory");
}
__device__ __forceinline__ void cp_commit() {
    asm volatile("cp.async.commit_group;" ::: "memory");
}
template <int N> __device__ __forceinline__ void cp_wait() {
    asm volatile("cp.async.wait_group %0;" :: "n"(N) : "memory");
}
__device__ __forceinline__ void ldmx4t(uint32_t* r, uint32_t addr) {
    asm volatile("ldmatrix.sync.aligned.m8n8.x4.trans.shared.b16 {%0,%1,%2,%3}, [%4];"
                 : "=r"(r[0]), "=r"(r[1]), "=r"(r[2]), "=r"(r[3]) : "r"(addr));
}
__device__ __forceinline__ void ldmx2t(uint32_t* r, uint32_t addr) {
    asm volatile("ldmatrix.sync.aligned.m8n8.x2.trans.shared.b16 {%0,%1}, [%2];"
                 : "=r"(r[0]), "=r"(r[1]) : "r"(addr));
}
__device__ __forceinline__ void ldmx4(uint32_t* r, uint32_t addr) {
    asm volatile("ldmatrix.sync.aligned.m8n8.x4.shared.b16 {%0,%1,%2,%3}, [%4];"
                 : "=r"(r[0]), "=r"(r[1]), "=r"(r[2]), "=r"(r[3]) : "r"(addr));
}
__device__ __forceinline__ void mma_f32(float* c, const uint32_t* a, const uint32_t* b) {
    asm volatile(
        "mma.sync.aligned.m16n8k16.row.col.f32.f16.f16.f32 "
        "{%0,%1,%2,%3}, {%4,%5,%6,%7}, {%8,%9}, {%0,%1,%2,%3};"
        : "+f"(c[0]), "+f"(c[1]), "+f"(c[2]), "+f"(c[3])
        : "r"(a[0]), "r"(a[1]), "r"(a[2]), "r"(a[3]), "r"(b[0]), "r"(b[1]));
}

// ---------------- prep: fp32 -> fp16 ----------------
__global__ void prep_all(const float* __restrict__ A, const float* __restrict__ B,
                         const float* __restrict__ gamma, const float* __restrict__ beta,
                         const float* __restrict__ W, const float* __restrict__ b) {
    if (blockIdx.x < 2048) {
        const unsigned v = blockIdx.x * 256 + threadIdx.x;  // float4 index
        const float4* src;
        __half* dh;
        unsigned i;
        if (v < 262144) { src = (const float4*)A; i = v; dh = g_Ah; }
        else            { src = (const float4*)B; i = v - 262144; dh = g_Bh; }
        const float4 x = src[i];
        __half2 h01 = __floats2half2_rn(x.x, x.y);
        __half2 h23 = __floats2half2_rn(x.z, x.w);
        ((uint2*)dh)[i] = make_uint2(*(uint32_t*)&h01, *(uint32_t*)&h23);
    } else {
        const int o = blockIdx.x - 2048;
        const int t = threadIdx.x;
        float s = 0.f;
        for (int k = t; k < KDIM; k += 256) {
            const float wv = W[o * KDIM + k];
            g_gWh[o * KDIM + k] = __float2half_rn(gamma[k] * wv);
            s += beta[k] * wv;
        }
        __shared__ float red[256];
        red[t] = s;
        __syncthreads();
        for (int st = 128; st > 0; st >>= 1) {
            if (t < st) red[t] += red[t + st];
            __syncthreads();
        }
        if (t == 0) g_cb[o] = b[o] + red[0];
    }
}

// ---------------- kernel A: GEMM1 + LN -> g_NpH (2-stage cp.async) ---------
__global__ __launch_bounds__(256, 2)
void coevol_g1_kernel() {
    extern __shared__ char sm[];
    const uint32_t SB = smem_u32(sm);

    const int tid = threadIdx.x;
    const int lane = tid & 31, w = tid >> 5;
    const int bx = blockIdx.x, by = blockIdx.y;

    const int mbase = (w & 3) * 32;
    const int nbase = (w >> 2) * 64;
    float acc[2][8][4];
#pragma unroll
    for (int mt = 0; mt < 2; ++mt)
#pragma unroll
        for (int nt = 0; nt < 8; ++nt)
#pragma unroll
            for (int c = 0; c < 4; ++c) acc[mt][nt][c] = 0.f;

    const int g4 = lane >> 3;
    const int grow = lane & 7;
    const int kadd4 = (g4 >> 1) * 8, madd4 = (g4 & 1) * 8;
    const int kadd2 = (g4 & 1) * 8;

    // staging: 4 cp16/thread/stage. v: buf = v>>9 (AH,BH); r=(v&511)>>4; c=v&15
    auto stage_load = [&](int ch) {
        const uint32_t stg = SB + (uint32_t)(ch & 1) * A_STAGE;
#pragma unroll
        for (int it = 0; it < 4; ++it) {
            const int v = it * 256 + tid;          // 0..1023
            const int buf = v >> 9;
            const int rem = v & 511;
            const int r = rem >> 4, c = rem & 15;
            const size_t srow = (size_t)(ch * 32 + r) * 16384;  // 8192 fp16/row
            const uint32_t dst = stg + (uint32_t)buf * 8704u
                               + (uint32_t)r * 272u + (uint32_t)c * 16u;
            const char* src = (buf == 0)
                ? (const char*)g_Ah + srow + bx * 256 + c * 16
                : (const char*)g_Bh + srow + by * 256 + c * 16;
            cp16(dst, src);
        }
    };

    stage_load(0);
    cp_commit();

    for (int ch = 0; ch < 4; ++ch) {
        cp_wait<0>();
        __syncthreads();
        if (ch < 3) { stage_load(ch + 1); cp_commit(); }

        const uint32_t stg = SB + (uint32_t)(ch & 1) * A_STAGE;
#pragma unroll
        for (int ks = 0; ks < 2; ++ks) {
            uint32_t ah[2][4];
#pragma unroll
            for (int mt = 0; mt < 2; ++mt) {
                const uint32_t aoff = (uint32_t)(ks * 16 + kadd4 + grow) * 272u
                                    + (uint32_t)(mbase + mt * 16 + madd4) * 2u;
                ldmx4t(ah[mt], stg + A_AH + aoff);
            }
#pragma unroll
            for (int nt = 0; nt < 8; ++nt) {
                uint32_t bh[2];
                const uint32_t boff = (uint32_t)(ks * 16 + kadd2 + grow) * 272u
                                    + (uint32_t)(nbase + nt * 8) * 2u;
                ldmx2t(bh, stg + A_BH + boff);
#pragma unroll
                for (int mt = 0; mt < 2; ++mt)
                    mma_f32(acc[mt][nt], ah[mt], bh);
            }
        }
    }
    __syncthreads();  // stage smem reuse for Np staging

    // ---------------- LayerNorm (warp-local) -> Np smem fp16 ----------
    const int i_loc = w & 3;
#pragma unroll
    for (int lb = 0; lb < 2; ++lb) {
        const int l_loc = (w >> 2) * 2 + lb;
        float sum = 0.f, sq = 0.f;
#pragma unroll
        for (int mt = 0; mt < 2; ++mt)
#pragma unroll
            for (int nt4 = 0; nt4 < 4; ++nt4)
#pragma unroll
                for (int c = 0; c < 4; ++c) {
                    const float v = acc[mt][lb * 4 + nt4][c];
                    sum += v;
                    sq = fmaf(v, v, sq);
                }
#pragma unroll
        for (int off = 16; off >= 1; off >>= 1) {
            sum += __shfl_xor_sync(0xffffffffu, sum, off);
            sq  += __shfl_xor_sync(0xffffffffu, sq, off);
        }
        const float mean = sum * (1.f / KDIM);
        const float var  = sq * (1.f / KDIM) - mean * mean;
        const float rstd = rsqrtf(var + LN_EPS);
        const int p = i_loc * 4 + l_loc;
#pragma unroll
        for (int mt = 0; mt < 2; ++mt)
#pragma unroll
            for (int nt4 = 0; nt4 < 4; ++nt4)
#pragma unroll
                for (int cp = 0; cp < 2; ++cp) {
                    const float f0 = (acc[mt][lb * 4 + nt4][cp * 2 + 0] - mean) * rstd;
                    const float f1 = (acc[mt][lb * 4 + nt4][cp * 2 + 1] - mean) * rstd;
                    __half2 h2 = __floats2half2_rn(f0, f1);
                    const int j  = mt * 16 + (lane >> 2) + cp * 8;
                    const int mc = nt4 * 4 + (lane & 3);
                    const int idx = p * 516 + j * 16 + (mc ^ ((j & 3) << 2));
                    *(uint32_t*)(sm + OFF_NPH + idx * 4) = *(uint32_t*)&h2;
                }
    }
    __syncthreads();

    // ---------------- copy Np smem -> global (coalesced) ----------
#pragma unroll
    for (int it = 0; it < 8; ++it) {
        const int v = it * 256 + tid;          // 0..2047 uint4
        const int p = v >> 7;
        const int c4 = v & 127;
        const int wb = c4 * 4;
        const int j = wb >> 4, mc = wb & 15;
        const int sidx = p * 516 + j * 16 + (mc ^ ((j & 3) << 2));
        const uint32_t* s = (const uint32_t*)(sm + OFF_NPH) + sidx;
        uint4 val = make_uint4(s[0], s[1], s[2], s[3]);
        const int gi = bx * 4 + (p >> 2);
        const int gl = by * 4 + (p & 3);
        const size_t pair = (size_t)gi * SEQ_L + gl;
        ((uint4*)g_NpH)[pair * 128 + c4] = val;
    }
}

// ---------------- kernel B: out = NpH . gWh + cb (3-stage cp.async) --------
// Grid 512: CTA = 128 pairs x 128 o, K = 1024 in 32 chunks of 32.
__global__ __launch_bounds__(256, 2)
void coevol_g2_kernel(float* __restrict__ out) {
    extern __shared__ char sm[];
    const uint32_t SB = smem_u32(sm);

    const int tid = threadIdx.x;
    const int lane = tid & 31, w = tid >> 5;
    const int pb = blockIdx.x;

    const int mp = (w & 3) * 32;
    const int ob = (w >> 2) * 64;

    float acc[2][8][4];
#pragma unroll
    for (int mt = 0; mt < 2; ++mt)
#pragma unroll
        for (int nt = 0; nt < 8; ++nt)
#pragma unroll
            for (int c = 0; c < 4; ++c) acc[mt][nt][c] = 0.f;

    const int rA = lane & 15, cAs = lane >> 4;
    const int rB = ((lane >> 4) << 3) + (lane & 7);
    const int cBs = (lane >> 3) & 1;

    // stage load: 4 cp16/thread. Np and gW rows 64 B, swizzle c^((r>>1)&3).
    auto stage_load = [&](int ch) {
        const uint32_t stg = SB + (uint32_t)(ch % 3) * B_STAGE;
#pragma unroll
        for (int it = 0; it < 4; ++it) {
            const int v = it * 256 + tid;     // 0..1023
            uint32_t dst;
            const char* src;
            if (v < 512) {                    // NpH
                const int r = v >> 2, c = v & 3;
                dst = stg + S_N + (uint32_t)(r * 64 + ((c ^ ((r >> 1) & 3)) << 4));
                src = (const char*)g_NpH + (size_t)(pb * 128 + r) * 2048
                    + ch * 64 + c * 16;
            } else {                          // gWh
                const int g = v - 512;        // 0..511
                const int r = g >> 2, c = g & 3;
                dst = stg + S_G + (uint32_t)(r * 64 + ((c ^ ((r >> 1) & 3)) << 4));
                src = (const char*)g_gWh + (size_t)r * 2048 + ch * 64 + c * 16;
            }
            cp16(dst, src);
        }
    };

    stage_load(0); cp_commit();
    stage_load(1); cp_commit();

    for (int ch = 0; ch < 32; ++ch) {
        if (ch < 31) cp_wait<1>(); else cp_wait<0>();
        __syncthreads();
        if (ch + 2 < 32) { stage_load(ch + 2); cp_commit(); }

        const uint32_t stg = SB + (uint32_t)(ch % 3) * B_STAGE;
#pragma unroll
        for (int ks = 0; ks < 2; ++ks) {
            const int cc = ks * 2;
            uint32_t ah[2][4];
#pragma unroll
            for (int mt = 0; mt < 2; ++mt) {
                const int r = mp + mt * 16 + rA;
                const int c = cc + cAs;
                ldmx4(ah[mt], stg + S_N
                      + (uint32_t)(r * 64 + ((c ^ ((r >> 1) & 3)) << 4)));
            }
#pragma unroll
            for (int n4 = 0; n4 < 4; ++n4) {
                uint32_t bh[4];
                const int r = ob + n4 * 16 + rB;
                const int c = cc + cBs;
                ldmx4(bh, stg + S_G
                      + (uint32_t)(r * 64 + ((c ^ ((r >> 1) & 3)) << 4)));
#pragma unroll
                for (int half = 0; half < 2; ++half) {
                    const int nt = n4 * 2 + half;
#pragma unroll
                    for (int mt = 0; mt < 2; ++mt)
                        mma_f32(acc[mt][nt], ah[mt], bh + half * 2);
                }
            }
        }
    }

    // ---------------- epilogue ----------------
#pragma unroll
    for (int nt = 0; nt < 8; ++nt) {
        const int o0 = ob + nt * 8 + 2 * (lane & 3);
        const float cb0 = g_cb[o0], cb1 = g_cb[o0 + 1];
#pragma unroll
        for (int mt = 0; mt < 2; ++mt) {
            const int r0 = mp + mt * 16 + (lane >> 2);
            const size_t pair0 = (size_t)pb * 128 + r0;
            float2 v0, v1;
            v0.x = acc[mt][nt][0] + cb0;
            v0.y = acc[mt][nt][1] + cb1;
            v1.x = acc[mt][nt][2] + cb0;
            v1.y = acc[mt][nt][3] + cb1;
            *(float2*)&out[pair0 * NOUT + o0] = v0;
            *(float2*)&out[(pair0 + 8) * NOUT + o0] = v1;
        }
    }
}

// ---------------------------------------------------------------------------
extern "C" void kernel_launch(void* const* d_in, const int* in_sizes, int n_in,
                              void* d_out, int out_size) {
    const float* x_down   = (const float*)d_in[0];
    const float* x_down_w = (const float*)d_in[1];
    const float* gamma    = (const float*)d_in[2];
    const float* beta     = (const float*)d_in[3];
    const float* W        = (const float*)d_in[4];
    const float* b        = (const float*)d_in[5];
    float* out = (float*)d_out;

    cudaFuncSetAttribute(coevol_g1_kernel,
                         cudaFuncAttributeMaxDynamicSharedMemorySize, SMEM_A_TOTAL);
    cudaFuncSetAttribute(coevol_g2_kernel,
                         cudaFuncAttributeMaxDynamicSharedMemorySize, SMEM_B_TOTAL);

    prep_all<<<2176, 256>>>(x_down, x_down_w, gamma, beta, W, b);

    dim3 grid1(SEQ_L / 4, SEQ_L / 4);  // 64 x 64
    coevol_g1_kernel<<<grid1, 256, SMEM_A_TOTAL>>>();

    coevol_g2_kernel<<<512, 256, SMEM_B_TOTAL>>>(out);
}